// round 17
// baseline (speedup 1.0000x reference)
#include <cuda_runtime.h>

#define NN 16384
#define E_EDGES 524288
#define KNB 16
#define NSEG 2
#define JSEG (NN/NSEG)
#define RB 64
#define JC 32

// ---------------- scratch (static device globals; no allocations) ----------------
__device__ float g_x1[NN*64];
__device__ float g_u [NN*64];
__device__ float g_v [NN*64];
__device__ float g_sq[NN];
__device__ int   g_knn[NN*KNB];
__device__ float g_pd[NSEG*NN*KNB];
__device__ int   g_pi[NSEG*NN*KNB];
__device__ int   g_ei32;   // 1 if edge_index buffer is int32, 0 if int64

// ---------------- f32x2 helpers ----------------
static __device__ __forceinline__ unsigned long long pk2(float lo, float hi){
    unsigned long long r;
    asm("mov.b64 %0, {%1,%2};" : "=l"(r) : "f"(lo), "f"(hi));
    return r;
}
static __device__ __forceinline__ void fma2(unsigned long long& acc,
                                            unsigned long long a, unsigned long long b){
    asm("fma.rn.f32x2 %0, %1, %2, %0;" : "+l"(acc) : "l"(a), "l"(b));
}
static __device__ __forceinline__ float2 upk2(unsigned long long v){
    float lo, hi;
    asm("mov.b64 {%0,%1}, %2;" : "=f"(lo), "=f"(hi) : "l"(v));
    return make_float2(lo, hi);
}

// Insert (d,j) into register-resident top-16, evicting the lexicographic max (d,idx).
static __device__ __forceinline__ void t16_insert(float (&bd)[16], int (&bi)[16],
                                                  float d, int j, float& mx, int& mxi){
    int pos = 0; float cd = bd[0]; int ci = bi[0];
#pragma unroll
    for (int t = 1; t < 16; t++){
        bool g = (bd[t] > cd) || (bd[t] == cd && bi[t] > ci);
        cd = g ? bd[t] : cd; ci = g ? bi[t] : ci; pos = g ? t : pos;
    }
#pragma unroll
    for (int t = 0; t < 16; t++) if (t == pos){ bd[t] = d; bi[t] = j; }
    cd = bd[0]; ci = bi[0];
#pragma unroll
    for (int t = 1; t < 16; t++){
        bool g = (bd[t] > cd) || (bd[t] == cd && bi[t] > ci);
        cd = g ? bd[t] : cd; ci = g ? bi[t] : ci;
    }
    mx = cd; mxi = ci;
}

// Shared-memory top-16 insert (stride RB): write over slot mxp, rescan for new max.
static __device__ __forceinline__ void t16s_insert(float* __restrict__ sbd,
                                                   int*   __restrict__ sbi,
                                                   float d, int j,
                                                   float& mx, int& mxi, int& mxp){
    sbd[mxp*RB] = d; sbi[mxp*RB] = j;
    float cd = sbd[0]; int ci = sbi[0]; int cp = 0;
#pragma unroll
    for (int t = 1; t < 16; t++){
        float bt = sbd[t*RB]; int it = sbi[t*RB];
        bool g = (bt > cd) || (bt == cd && it > ci);
        cd = g ? bt : cd; ci = g ? it : ci; cp = g ? t : cp;
    }
    mx = cd; mxi = ci; mxp = cp;
}

// ---------------- edge_index dtype detection ----------------
__global__ void k_detect(const int* __restrict__ ei){
    __shared__ int nz;
    if (threadIdx.x == 0) nz = 0;
    __syncthreads();
    int c = 0;
    for (int t = threadIdx.x; t < 4096; t += blockDim.x)
        if (ei[2*t + 1] != 0) c = 1;
    if (c) atomicOr(&nz, 1);
    __syncthreads();
    if (threadIdx.x == 0) g_ei32 = nz;
}

// ---------------- init: zero x1 accumulator and output ----------------
__global__ void k_init(float* __restrict__ out){
    int i = blockIdx.x*blockDim.x + threadIdx.x;
    if (i < NN*64){ g_x1[i] = 0.f; out[i] = 0.f; }
}

// ---------------- per-node affine split of layer 1 ----------------
template<int CIN, bool SQ, bool FROMX1>
__global__ void __launch_bounds__(256) k_node(const float* __restrict__ xin,
                                              const float* __restrict__ W,
                                              const float* __restrict__ bias){
    __shared__ __align__(16) float sW[2*CIN*64];
    __shared__ __align__(16) float sb[64];
    for (int t = threadIdx.x; t < 2*CIN*64; t += blockDim.x) sW[t] = W[t];
    if (threadIdx.x < 64) sb[threadIdx.x] = bias[threadIdx.x];
    __syncthreads();

    int i = blockIdx.x*blockDim.x + threadIdx.x;
    const float* xb = FROMX1 ? (const float*)g_x1 : xin;
    float xr[CIN];
#pragma unroll
    for (int k = 0; k < CIN; k++) xr[k] = xb[i*CIN + k];
    if (SQ){
        float s = 0.f;
#pragma unroll
        for (int k = 0; k < CIN; k++) s += xr[k]*xr[k];
        g_sq[i] = s;
    }
    for (int cq = 0; cq < 16; cq++){
        float4 au = make_float4(0.f,0.f,0.f,0.f);
        float4 av = make_float4(0.f,0.f,0.f,0.f);
#pragma unroll
        for (int k = 0; k < CIN; k++){
            float4 wt = *(const float4*)(sW + k*64 + cq*4);
            float4 wb = *(const float4*)(sW + (CIN+k)*64 + cq*4);
            float p = xr[k];
            au.x += p*wt.x; au.y += p*wt.y; au.z += p*wt.z; au.w += p*wt.w;
            av.x += p*wb.x; av.y += p*wb.y; av.z += p*wb.z; av.w += p*wb.w;
        }
        float4 bb = *(const float4*)(sb + cq*4);
        float4 uo;
        uo.x = bb.x + au.x - av.x; uo.y = bb.y + au.y - av.y;
        uo.z = bb.z + au.z - av.z; uo.w = bb.w + au.w - av.w;
        *(float4*)(g_u + i*64 + cq*4) = uo;
        *(float4*)(g_v + i*64 + cq*4) = av;
    }
}

// ---------------- per-edge: ReLU(u+v) -> 64x64 layer-2 -> ReLU -> atomic seg-max ----------
static __device__ __forceinline__ void edge_tail(int dst, int src,
                                                 const float* __restrict__ sWt,
                                                 const float* __restrict__ sb,
                                                 float* __restrict__ outb){
    const float4* up = (const float4*)(g_u + dst*64);
    const float4* vp = (const float4*)(g_v + src*64);
    unsigned long long h1p[32];
#pragma unroll
    for (int q = 0; q < 16; q++){
        float4 a = up[q], b = vp[q];
        h1p[2*q  ] = pk2(fmaxf(a.x+b.x,0.f), fmaxf(a.y+b.y,0.f));
        h1p[2*q+1] = pk2(fmaxf(a.z+b.z,0.f), fmaxf(a.w+b.w,0.f));
    }
    int* orow = (int*)outb + dst*64;
    for (int c = 0; c < 64; c++){
        const ulonglong2* w = (const ulonglong2*)(sWt + c*64);
        unsigned long long a0 = pk2(sb[c], 0.f), a1 = 0ull, a2 = 0ull, a3 = 0ull;
#pragma unroll
        for (int q = 0; q < 16; q += 2){
            ulonglong2 w0 = w[q], w1 = w[q+1];
            fma2(a0, h1p[2*q  ], w0.x);
            fma2(a1, h1p[2*q+1], w0.y);
            fma2(a2, h1p[2*q+2], w1.x);
            fma2(a3, h1p[2*q+3], w1.y);
        }
        float2 r0 = upk2(a0), r1 = upk2(a1), r2 = upk2(a2), r3 = upk2(a3);
        float s = ((r0.x+r0.y)+(r1.x+r1.y)) + ((r2.x+r2.y)+(r3.x+r3.y));
        if (s > 0.f) atomicMax(orow + c, __float_as_int(s));  // non-negative floats: int-max == float-max
    }
}

__global__ void __launch_bounds__(256) k_ec1(const void* __restrict__ ei,
                                             const float* __restrict__ W2,
                                             const float* __restrict__ b2){
    __shared__ __align__(16) float sWt[64*64];
    __shared__ __align__(16) float sb[64];
    for (int t = threadIdx.x; t < 4096; t += blockDim.x){
        int k = t >> 6, c = t & 63;
        sWt[c*64 + k] = W2[t];                       // transpose: contiguous over k
    }
    if (threadIdx.x < 64) sb[threadIdx.x] = b2[threadIdx.x];
    __syncthreads();
    int e = blockIdx.x*blockDim.x + threadIdx.x;
    int src, dst;
    if (g_ei32){
        const int* e32 = (const int*)ei;
        src = e32[e];                    // edge_index[0] = source j
        dst = e32[E_EDGES + e];          // edge_index[1] = target i
    } else {
        const long long* e64 = (const long long*)ei;
        src = (int)e64[e];
        dst = (int)e64[E_EDGES + e];
    }
    if ((unsigned)src < NN && (unsigned)dst < NN)
        edge_tail(dst, src, sWt, sb, g_x1);
}

__global__ void __launch_bounds__(256) k_ec2(const float* __restrict__ W4,
                                             const float* __restrict__ b4,
                                             float* __restrict__ out){
    __shared__ __align__(16) float sWt[64*64];
    __shared__ __align__(16) float sb[64];
    for (int t = threadIdx.x; t < 4096; t += blockDim.x){
        int k = t >> 6, c = t & 63;
        sWt[c*64 + k] = W4[t];
    }
    if (threadIdx.x < 64) sb[threadIdx.x] = b4[threadIdx.x];
    __syncthreads();
    int e = blockIdx.x*blockDim.x + threadIdx.x;
    int dst = e >> 4;
    int src = g_knn[e];
    edge_tail(dst, src, sWt, sb, out);
}

// ---------------- kNN: 2D register tiling (4 rows x 4 j per thread) + scan phase --------
// Block: 128 threads, 64 rows, 32-j chunks. Both operands from smem -> LDS per dot
// halves (8 LDS.128 vs 16). XOR swizzle col^=((row>>2)&7)<<2 -> conflict-free A loads.
__global__ void __launch_bounds__(128, 4) k_knn(){
    __shared__ __align__(16) float sxi[RB*64];   // 16KB, swizzled
    __shared__ __align__(16) float sxj[JC*64];   // 8KB, swizzled
    __shared__ __align__(16) float sD [RB*JC];   // 8KB, swizzled
    __shared__ float ssqj[JC];
    __shared__ float sbd[16*RB];                 // 4KB  [slot][row]
    __shared__ int   sbi[16*RB];                 // 4KB
    int tid = threadIdx.x;
    int rowbase = blockIdx.x*RB;
    int j0 = blockIdx.y*JSEG;
    int rg = tid >> 3;      // 0..15 : rows rg*4 .. rg*4+3
    int jg = tid & 7;       // 0..7  : j    jg*4 .. jg*4+3

    // load row tile (once) with swizzle
    {
        const float4* g = (const float4*)(g_x1 + (size_t)rowbase*64);
#pragma unroll
        for (int k = 0; k < (RB*16)/128; k++){
            int i = tid + k*128;
            int row = i >> 4, col = (i & 15) << 2;
            int w = row*64 + (col ^ (((row>>2)&7) << 2));
            *(float4*)(sxi + w) = g[i];
        }
    }
    float sqi = 0.f;
    if (tid < RB){
#pragma unroll
        for (int t = 0; t < 16; t++){
            sbd[t*RB + tid] = __int_as_float(0x7f800000);
            sbi[t*RB + tid] = 0x7fffffff;
        }
        sqi = g_sq[rowbase + tid];
    }
    float mx = __int_as_float(0x7f800000); int mxi = 0x7fffffff; int mxp = 0;

    for (int ch = 0; ch < JSEG; ch += JC){
        __syncthreads();
        // load j tile with swizzle
        {
            const float4* gj = (const float4*)(g_x1 + (size_t)(j0+ch)*64);
#pragma unroll
            for (int k = 0; k < (JC*16)/128; k++){
                int i = tid + k*128;
                int row = i >> 4, col = (i & 15) << 2;
                int w = row*64 + (col ^ (((row>>2)&7) << 2));
                *(float4*)(sxj + w) = gj[i];
            }
        }
        if (tid < JC) ssqj[tid] = g_sq[j0 + ch + tid];
        __syncthreads();

        // Phase A: 4x4 dot tile
        unsigned long long a[16];
#pragma unroll
        for (int t = 0; t < 16; t++) a[t] = 0ull;
#pragma unroll
        for (int fi = 0; fi < 16; fi++){
            int f = fi << 2;
            ulonglong2 xiv[4], xjv[4];
#pragma unroll
            for (int r = 0; r < 4; r++){
                int w = (rg*4 + r)*64 + (f ^ ((rg & 7) << 2));
                xiv[r] = *(const ulonglong2*)(sxi + w);
            }
#pragma unroll
            for (int c = 0; c < 4; c++){
                int w = (jg*4 + c)*64 + (f ^ (jg << 2));
                xjv[c] = *(const ulonglong2*)(sxj + w);
            }
#pragma unroll
            for (int r = 0; r < 4; r++)
#pragma unroll
                for (int c = 0; c < 4; c++){
                    fma2(a[r*4+c], xiv[r].x, xjv[c].x);
                    fma2(a[r*4+c], xiv[r].y, xjv[c].y);
                }
        }
        // write partial distances d' = sqj - 2*dot (sqi added in scan; constant per row)
        float sq0 = ssqj[jg*4+0], sq1 = ssqj[jg*4+1], sq2 = ssqj[jg*4+2], sq3 = ssqj[jg*4+3];
#pragma unroll
        for (int r = 0; r < 4; r++){
            int row = rg*4 + r;
            float2 q0 = upk2(a[r*4+0]), q1 = upk2(a[r*4+1]);
            float2 q2 = upk2(a[r*4+2]), q3 = upk2(a[r*4+3]);
            float4 dv;
            dv.x = sq0 - 2.f*(q0.x+q0.y);
            dv.y = sq1 - 2.f*(q1.x+q1.y);
            dv.z = sq2 - 2.f*(q2.x+q2.y);
            dv.w = sq3 - 2.f*(q3.x+q3.y);
            int w = row*JC + ((jg << 2) ^ ((row & 7) << 2));
            *(float4*)(sD + w) = dv;
        }
        __syncthreads();

        // Phase B: scan (one thread per row)
        if (tid < RB){
            int row = tid;
            int sw = (row & 7) << 2;
#pragma unroll
            for (int j4 = 0; j4 < JC/4; j4++){
                int w = row*JC + ((j4 << 2) ^ sw);
                float4 dv = *(const float4*)(sD + w);
                float d0 = sqi + dv.x, d1 = sqi + dv.y, d2 = sqi + dv.z, d3 = sqi + dv.w;
                // ascending j + strict < reproduces lax.top_k tie order exactly
                if ((d0 < mx) | (d1 < mx) | (d2 < mx) | (d3 < mx)){
                    int jb = j0 + ch + (j4 << 2);
                    if (d0 < mx) t16s_insert(sbd+tid, sbi+tid, d0, jb+0, mx, mxi, mxp);
                    if (d1 < mx) t16s_insert(sbd+tid, sbi+tid, d1, jb+1, mx, mxi, mxp);
                    if (d2 < mx) t16s_insert(sbd+tid, sbi+tid, d2, jb+2, mx, mxi, mxp);
                    if (d3 < mx) t16s_insert(sbd+tid, sbi+tid, d3, jb+3, mx, mxi, mxp);
                }
            }
        }
    }
    if (tid < RB){
        int base = (blockIdx.y*NN + rowbase + tid)*KNB;
#pragma unroll
        for (int t = 0; t < 16; t++){
            g_pd[base+t] = sbd[t*RB + tid];
            g_pi[base+t] = sbi[t*RB + tid];
        }
    }
}

// ---------------- merge per-segment top-16s into global top-16 set ----------------
__global__ void __launch_bounds__(256) k_merge(){
    int i = blockIdx.x*blockDim.x + threadIdx.x;
    float bd[16]; int bi[16];
#pragma unroll
    for (int t = 0; t < 16; t++){ bd[t] = __int_as_float(0x7f800000); bi[t] = 0x7fffffff; }
    float mx = __int_as_float(0x7f800000); int mxi = 0x7fffffff;
    for (int s = 0; s < NSEG; s++){
        int base = (s*NN + i)*KNB;
#pragma unroll
        for (int t = 0; t < 16; t++){
            float d = g_pd[base+t]; int j = g_pi[base+t];
            if (d < mx || (d == mx && j < mxi)){
                t16_insert(bd, bi, d, j, mx, mxi);
            }
        }
    }
#pragma unroll
    for (int t = 0; t < 16; t++) g_knn[i*KNB + t] = bi[t];
}

// ---------------- launch ----------------
extern "C" void kernel_launch(void* const* d_in, const int* in_sizes, int n_in,
                              void* d_out, int out_size){
    const float* x  = (const float*)d_in[0];
    const void*  ei = d_in[1];
    int off = (n_in > 2 && in_sizes[2] == 1) ? 3 : 2;
    const float* W1 = (const float*)d_in[off+0];
    const float* b1 = (const float*)d_in[off+1];
    const float* W2 = (const float*)d_in[off+2];
    const float* b2 = (const float*)d_in[off+3];
    const float* W3 = (const float*)d_in[off+4];
    const float* b3 = (const float*)d_in[off+5];
    const float* W4 = (const float*)d_in[off+6];
    const float* b4 = (const float*)d_in[off+7];
    float* out = (float*)d_out;

    k_detect<<<1, 256>>>((const int*)ei);
    k_init<<<(NN*64)/256, 256>>>(out);
    // EdgeConv1
    k_node<3, false, false><<<NN/256, 256>>>(x, W1, b1);
    k_ec1<<<E_EDGES/256, 256>>>(ei, W2, b2);
    // node-level work for EdgeConv2 layer-1 + sq-norms of x1 for kNN
    k_node<64, true, true><<<NN/256, 256>>>(nullptr, W3, b3);
    // kNN in x1 feature space (2D-tiled GEMM + scan)
    dim3 kg(NN/RB, NSEG);
    k_knn<<<kg, 128>>>();
    k_merge<<<NN/256, 256>>>();
    // EdgeConv2
    k_ec2<<<(NN*KNB)/256, 256>>>(W4, b4, out);
    (void)in_sizes; (void)n_in; (void)out_size;
}